// round 3
// baseline (speedup 1.0000x reference)
#include <cuda_runtime.h>

#define B  512
#define NN 64
#define NE 1024
#define DD 128
#define BN (B*NN)      // 32768
#define BE (B*NE)      // 524288

// ---------------- scratch (device globals; no allocation) ----------------
__device__ __align__(16) float g_s0buf[BN*DD];
__device__ __align__(16) float g_s1buf[BN*DD];
__device__ __align__(16) float g_p[BN*DD];
__device__ float g_rs[BN];
__device__ __align__(16) float g_R[DD*DD];        // W_link^T  : [k][o]
__device__ __align__(16) float g_WrT[2*DD*DD];    // W_r^T     : [k][o], k in [0,256)
__device__ __align__(16) float g_WzT[2*DD*DD];
__device__ __align__(16) float g_WhT[2*DD*DD];
__device__ __align__(16) float g_WoT[DD*DD];
__device__ __align__(16) float g_Wa1T[DD*DD];
__device__ __align__(16) float g_P[2][DD*DD];     // powers of R
__device__ __align__(16) float g_cc[2][DD];       // composed bias
__device__ float g_respart[B*16*DD];              // per-(b, e-chunk) colsums of e0
__device__ float g_resid[B*DD];
__device__ float g_attl[BN];

// ---------------- weight prep: transposes ----------------
__global__ void __launch_bounds__(256) prep_weights(
    const float* __restrict__ Wl, const float* __restrict__ bl,
    const float* __restrict__ Wr, const float* __restrict__ Wz,
    const float* __restrict__ Wh, const float* __restrict__ Wo,
    const float* __restrict__ Wa1)
{
    int idx = blockIdx.x*256 + threadIdx.x;   // 0..32767
    int k = idx >> 7, o = idx & 127;
    g_WrT[idx] = Wr[o*256 + k];
    g_WzT[idx] = Wz[o*256 + k];
    g_WhT[idx] = Wh[o*256 + k];
    if (idx < DD*DD) {
        float v = Wl[o*DD + k];
        g_R[idx] = v;
        g_P[0][idx] = v;
        g_WoT[idx]  = Wo[o*DD + k];
        g_Wa1T[idx] = Wa1[o*DD + k];
    }
    if (idx < DD) g_cc[0][idx] = bl[idx];
}

// P_{t+1} = P_t @ R ; c_{t+1} = c_t @ R + b    (4 applications -> R^5, c5)
__global__ void __launch_bounds__(128) compose_step(int s, const float* __restrict__ bl)
{
    __shared__ float row[DD];
    __shared__ float crow[DD];
    int src = s & 1, dst = src ^ 1;
    int i = blockIdx.x, o = threadIdx.x;
    row[o]  = g_P[src][i*DD + o];
    crow[o] = (i == 0) ? g_cc[src][o] : 0.f;
    __syncthreads();
    float acc = 0.f, cacc = 0.f;
    #pragma unroll 8
    for (int m = 0; m < DD; m++) {
        float rv = g_R[m*DD + o];
        acc  += row[m]  * rv;
        cacc += crow[m] * rv;
    }
    g_P[dst][i*DD + o] = acc;
    if (i == 0) g_cc[dst][o] = cacc + bl[o];
}

__global__ void __launch_bounds__(256) copy_p(const float* __restrict__ p0)
{
    int i = blockIdx.x*256 + threadIdx.x;
    g_p[i] = p0[i];
}

// ---------------- s0 = A @ e0 (per batch), + rowsum(A) ----------------
__global__ void __launch_bounds__(256) k_s0(const float* __restrict__ A,
                                            const float* __restrict__ E0)
{
    __shared__ float sA[64][37];
    __shared__ __align__(16) float sE[32][68];
    const int b = blockIdx.x, c0 = blockIdx.y*64;
    const int tid = threadIdx.x;
    const int tx = tid & 15, ty = tid >> 4;
    const float* Ab = A  + b*NN*NE;
    const float* Eb = E0 + b*NE*DD;
    float acc[4][4] = {};
    float rsum = 0.f;

    for (int k0 = 0; k0 < NE; k0 += 32) {
        #pragma unroll
        for (int i = 0; i < 8; i++) {
            int e = tid + i*256; int r = e >> 5, kk = e & 31;
            sA[r][kk] = Ab[r*NE + k0 + kk];
        }
        #pragma unroll
        for (int i = 0; i < 8; i++) {
            int e = tid + i*256; int kk = e >> 6, c = e & 63;
            sE[kk][c] = Eb[(k0+kk)*DD + c0 + c];
        }
        __syncthreads();
        if (blockIdx.y == 0 && tid < 64) {
            #pragma unroll
            for (int kk = 0; kk < 32; kk++) rsum += sA[tid][kk];
        }
        #pragma unroll
        for (int kk = 0; kk < 32; kk++) {
            float4 wv = *(const float4*)&sE[kk][tx*4];
            #pragma unroll
            for (int j = 0; j < 4; j++) {
                float av = sA[ty + 16*j][kk];
                acc[j][0] += av*wv.x; acc[j][1] += av*wv.y;
                acc[j][2] += av*wv.z; acc[j][3] += av*wv.w;
            }
        }
        __syncthreads();
    }
    #pragma unroll
    for (int j = 0; j < 4; j++) {
        int r = ty + 16*j;
        *(float4*)&g_s0buf[(b*NN + r)*DD + c0 + tx*4] =
            make_float4(acc[j][0], acc[j][1], acc[j][2], acc[j][3]);
    }
    if (blockIdx.y == 0 && tid < 64) g_rs[b*NN + tid] = rsum;
}

// ---------------- e5 = e0 @ R^5 + c5 ; partial colsums for residual ----------------
__global__ void __launch_bounds__(256) k_e5(const float* __restrict__ E0,
                                            float* __restrict__ outE)
{
    __shared__ __align__(16) float sX[64][132];
    __shared__ __align__(16) float sW[16][132];
    const int b = blockIdx.x, r0g = blockIdx.y*64;
    const int tid = threadIdx.x;
    const int tx = tid & 31, ty = tid >> 5;
    const int col = tx*4;
    const float* Eb = E0 + (b*NE + r0g)*DD;

    #pragma unroll
    for (int i = 0; i < 32; i++) {
        int e = tid + i*256; int r = e >> 7, c = e & 127;
        sX[r][c] = Eb[r*DD + c];
    }
    __syncthreads();

    float acc[8][4] = {};
    for (int k0 = 0; k0 < DD; k0 += 16) {
        #pragma unroll
        for (int i = 0; i < 8; i++) {
            int e = tid + i*256; int kk = e >> 7, o = e & 127;
            sW[kk][o] = g_P[0][(k0+kk)*DD + o];
        }
        __syncthreads();
        #pragma unroll
        for (int kk = 0; kk < 16; kk++) {
            float4 wv = *(const float4*)&sW[kk][col];
            #pragma unroll
            for (int j = 0; j < 8; j++) {
                float xv = sX[ty + 8*j][k0+kk];
                acc[j][0] += xv*wv.x; acc[j][1] += xv*wv.y;
                acc[j][2] += xv*wv.z; acc[j][3] += xv*wv.w;
            }
        }
        __syncthreads();
    }
    float c5a = g_cc[0][col+0], c5b = g_cc[0][col+1],
          c5c = g_cc[0][col+2], c5d = g_cc[0][col+3];
    #pragma unroll
    for (int j = 0; j < 8; j++) {
        int r = ty + 8*j;
        *(float4*)&outE[(b*NE + r0g + r)*DD + col] =
            make_float4(acc[j][0]+c5a, acc[j][1]+c5b, acc[j][2]+c5c, acc[j][3]+c5d);
    }
    // residual: colsum of this 64-row e0 tile (deterministic partials, no atomics)
    if (tid < 128) {
        float s = 0.f;
        #pragma unroll
        for (int r = 0; r < 64; r++) s += sX[r][tid];
        g_respart[(b*16 + blockIdx.y)*DD + tid] = s;
    }
}

// residual = sum_n p0 + sum over 16 edge partials   (divide later)
__global__ void __launch_bounds__(128) k_residual(const float* __restrict__ p0)
{
    int b = blockIdx.x, d = threadIdx.x;
    float s = 0.f;
    #pragma unroll
    for (int c = 0; c < 16; c++) s += g_respart[(b*16 + c)*DD + d];
    for (int n = 0; n < NN; n++)  s += p0[(b*NN + n)*DD + d];
    g_resid[b*DD + d] = s;
}

// ---------------- fused GRU step helpers ----------------
__device__ __forceinline__ void gemm256(const float* __restrict__ WT,
    const float (*sL)[132], const float (*sH)[132], float (*sWb)[132],
    int r0, int r1, int col, int tid, float a0[4], float a1[4])
{
    #pragma unroll
    for (int half = 0; half < 2; half++) {
        const float (*src)[132] = half ? sH : sL;
        for (int k0 = 0; k0 < 128; k0 += 32) {
            #pragma unroll
            for (int i = 0; i < 16; i++) {
                int e = tid + i*256; int kk = e >> 7, o = e & 127;
                sWb[kk][o] = WT[(half*128 + k0 + kk)*DD + o];
            }
            __syncthreads();
            #pragma unroll
            for (int kk = 0; kk < 32; kk++) {
                float4 wv = *(const float4*)&sWb[kk][col];
                float x0 = src[r0][k0+kk], x1 = src[r1][k0+kk];
                a0[0]+=x0*wv.x; a0[1]+=x0*wv.y; a0[2]+=x0*wv.z; a0[3]+=x0*wv.w;
                a1[0]+=x1*wv.x; a1[1]+=x1*wv.y; a1[2]+=x1*wv.z; a1[3]+=x1*wv.w;
            }
            __syncthreads();
        }
    }
}

__device__ __forceinline__ void gemm128(const float* __restrict__ WT,
    const float (*src)[132], float (*sWb)[132],
    int r0, int r1, int col, int tid, float a0[4], float a1[4])
{
    for (int k0 = 0; k0 < 128; k0 += 32) {
        #pragma unroll
        for (int i = 0; i < 16; i++) {
            int e = tid + i*256; int kk = e >> 7, o = e & 127;
            sWb[kk][o] = WT[(k0 + kk)*DD + o];
        }
        __syncthreads();
        #pragma unroll
        for (int kk = 0; kk < 32; kk++) {
            float4 wv = *(const float4*)&sWb[kk][col];
            float x0 = src[r0][k0+kk], x1 = src[r1][k0+kk];
            a0[0]+=x0*wv.x; a0[1]+=x0*wv.y; a0[2]+=x0*wv.z; a0[3]+=x0*wv.w;
            a1[0]+=x1*wv.x; a1[1]+=x1*wv.y; a1[2]+=x1*wv.z; a1[3]+=x1*wv.w;
        }
        __syncthreads();
    }
}

// one propagation step: a = s@R + rs*b_link ; r,z,h ; p update. s_out = a.
__global__ void __launch_bounds__(256) gru_step(int flip,
    const float* __restrict__ br, const float* __restrict__ bz,
    const float* __restrict__ bh, const float* __restrict__ bl)
{
    __shared__ __align__(16) float sXX[16][132];  // s_in, later r*p
    __shared__ __align__(16) float sAA[16][132];  // a
    __shared__ __align__(16) float sPP[16][132];  // p
    __shared__ __align__(16) float sW[32][132];
    const float* s_in  = flip ? g_s1buf : g_s0buf;
    float*       s_out = flip ? g_s0buf : g_s1buf;
    const int rb  = blockIdx.x * 16;
    const int tid = threadIdx.x;
    const int tx  = tid & 31, ty = tid >> 5;
    const int r0  = ty*2, r1 = r0 + 1;
    const int col = tx*4;

    #pragma unroll
    for (int i = 0; i < 8; i++) {
        int e = tid + i*256; int r = e >> 7, c = e & 127;
        sXX[r][c] = s_in[(rb+r)*DD + c];
        sPP[r][c] = g_p[(rb+r)*DD + c];
    }
    __syncthreads();
    const float rs0 = g_rs[rb+r0], rs1 = g_rs[rb+r1];

    // phase 1: a = s @ R + rs*b_link
    float A0[4] = {}, A1[4] = {};
    gemm128(g_R, sXX, sW, r0, r1, col, tid, A0, A1);
    #pragma unroll
    for (int q = 0; q < 4; q++) {
        float blv = bl[col+q];
        A0[q] += rs0*blv; A1[q] += rs1*blv;
        sAA[r0][col+q] = A0[q];
        sAA[r1][col+q] = A1[q];
    }
    *(float4*)&s_out[(rb+r0)*DD + col] = make_float4(A0[0],A0[1],A0[2],A0[3]);
    *(float4*)&s_out[(rb+r1)*DD + col] = make_float4(A1[0],A1[1],A1[2],A1[3]);
    __syncthreads();

    // phase 2: r gate, stash r*p into sXX
    float R0[4] = {}, R1[4] = {};
    gemm256(g_WrT, sAA, sPP, sW, r0, r1, col, tid, R0, R1);
    #pragma unroll
    for (int q = 0; q < 4; q++) {
        float b_ = br[col+q];
        float rv0 = 1.f/(1.f + __expf(-(R0[q]+b_)));
        float rv1 = 1.f/(1.f + __expf(-(R1[q]+b_)));
        sXX[r0][col+q] = rv0 * sPP[r0][col+q];
        sXX[r1][col+q] = rv1 * sPP[r1][col+q];
    }
    __syncthreads();

    // phase 3: z gate (kept in regs)
    float Z0[4] = {}, Z1[4] = {};
    gemm256(g_WzT, sAA, sPP, sW, r0, r1, col, tid, Z0, Z1);

    // phase 4: h_hat from [a, r*p], then p update
    float H0[4] = {}, H1[4] = {};
    gemm256(g_WhT, sAA, sXX, sW, r0, r1, col, tid, H0, H1);

    float P0[4], P1[4];
    #pragma unroll
    for (int q = 0; q < 4; q++) {
        float bz_ = bz[col+q], bh_ = bh[col+q];
        float z0 = 1.f/(1.f + __expf(-(Z0[q]+bz_)));
        float z1 = 1.f/(1.f + __expf(-(Z1[q]+bz_)));
        float h0 = tanhf(H0[q] + bh_);
        float h1 = tanhf(H1[q] + bh_);
        float p0v = sPP[r0][col+q], p1v = sPP[r1][col+q];
        P0[q] = (1.f - z0)*p0v + z0*h0;
        P1[q] = (1.f - z1)*p1v + z1*h1;
    }
    *(float4*)&g_p[(rb+r0)*DD + col] = make_float4(P0[0],P0[1],P0[2],P0[3]);
    *(float4*)&g_p[(rb+r1)*DD + col] = make_float4(P1[0],P1[1],P1[2],P1[3]);
}

// ---------------- epilogue: out = tanh(p@WoT+bo), attention logits ----------------
__global__ void __launch_bounds__(256) k_att(
    const float* __restrict__ bo, const float* __restrict__ ba1,
    const float* __restrict__ Wa2, const float* __restrict__ ba2,
    float* __restrict__ outO)
{
    __shared__ __align__(16) float sPP[16][132];
    __shared__ __align__(16) float sA1[16][132];
    __shared__ __align__(16) float sW[32][132];
    const int rb  = blockIdx.x * 16;
    const int tid = threadIdx.x;
    const int tx  = tid & 31, ty = tid >> 5;
    const int r0  = ty*2, r1 = r0 + 1;
    const int col = tx*4;

    #pragma unroll
    for (int i = 0; i < 8; i++) {
        int e = tid + i*256; int r = e >> 7, c = e & 127;
        sPP[r][c] = g_p[(rb+r)*DD + c];
    }
    __syncthreads();

    float O0[4] = {}, O1[4] = {};
    gemm128(g_WoT, sPP, sW, r0, r1, col, tid, O0, O1);
    #pragma unroll
    for (int q = 0; q < 4; q++) {
        float b_ = bo[col+q];
        O0[q] = tanhf(O0[q] + b_);
        O1[q] = tanhf(O1[q] + b_);
    }
    *(float4*)&outO[(rb+r0)*DD + col] = make_float4(O0[0],O0[1],O0[2],O0[3]);
    *(float4*)&outO[(rb+r1)*DD + col] = make_float4(O1[0],O1[1],O1[2],O1[3]);

    float T0[4] = {}, T1[4] = {};
    gemm128(g_Wa1T, sPP, sW, r0, r1, col, tid, T0, T1);
    #pragma unroll
    for (int q = 0; q < 4; q++) {
        float b_ = ba1[col+q];
        sA1[r0][col+q] = tanhf(T0[q] + b_);
        sA1[r1][col+q] = tanhf(T1[q] + b_);
    }
    __syncthreads();

    float d0 = 0.f, d1 = 0.f;
    for (int k = tx; k < 128; k += 32) {
        float w = Wa2[k];
        d0 += sA1[r0][k]*w;
        d1 += sA1[r1][k]*w;
    }
    #pragma unroll
    for (int off = 16; off; off >>= 1) {
        d0 += __shfl_xor_sync(0xFFFFFFFFu, d0, off);
        d1 += __shfl_xor_sync(0xFFFFFFFFu, d1, off);
    }
    if (tx == 0) {
        float bb = ba2[0];
        g_attl[rb+r0] = d0 + bb;
        g_attl[rb+r1] = d1 + bb;
    }
}

// softmax over nodes, weighted sum, residual, relu
__global__ void __launch_bounds__(128) k_final(const float* __restrict__ outO,
                                               float* __restrict__ res)
{
    __shared__ float sl[64];
    __shared__ float se[64];
    const int b = blockIdx.x, tid = threadIdx.x;
    if (tid < 64) sl[tid] = g_attl[b*NN + tid];
    __syncthreads();
    float mx = -1e30f;
    #pragma unroll
    for (int n = 0; n < 64; n++) mx = fmaxf(mx, sl[n]);
    if (tid < 64) se[tid] = __expf(sl[tid] - mx);
    __syncthreads();
    float sum = 0.f;
    #pragma unroll
    for (int n = 0; n < 64; n++) sum += se[n];
    const float* ob = outO + (b*NN)*DD + tid;
    float ws = 0.f;
    #pragma unroll 8
    for (int n = 0; n < 64; n++) ws += se[n]*ob[n*DD];
    float g  = tanhf(ws / sum);
    float rr = g + g_resid[b*DD + tid] * (1.f/1088.f);
    res[b*DD + tid] = fmaxf(rr, 0.f);
}

// ---------------- launch ----------------
extern "C" void kernel_launch(void* const* d_in, const int* in_sizes, int n_in,
                              void* d_out, int out_size)
{
    const float* in_prop = (const float*)d_in[0];
    const float* in_edge = (const float*)d_in[1];
    const float* in_A    = (const float*)d_in[2];
    const float* Wl  = (const float*)d_in[3];
    const float* bl  = (const float*)d_in[4];
    const float* Wr  = (const float*)d_in[5];
    const float* br  = (const float*)d_in[6];
    const float* Wz  = (const float*)d_in[7];
    const float* bz  = (const float*)d_in[8];
    const float* Wh  = (const float*)d_in[9];
    const float* bh  = (const float*)d_in[10];
    const float* Wa1 = (const float*)d_in[11];
    const float* ba1 = (const float*)d_in[12];
    const float* Wa2 = (const float*)d_in[13];
    const float* ba2 = (const float*)d_in[14];
    const float* Wo  = (const float*)d_in[15];
    const float* bo  = (const float*)d_in[16];

    float* out  = (float*)d_out;
    float* res  = out;                       // [512,128]
    float* outO = out + B*DD;                // [512,64,128]
    float* outE = out + B*DD + BN*DD;        // [512,1024,128]

    copy_p<<<BN*DD/256, 256>>>(in_prop);
    prep_weights<<<128, 256>>>(Wl, bl, Wr, Wz, Wh, Wo, Wa1);
    for (int s = 0; s < 4; s++) compose_step<<<128, 128>>>(s, bl);

    k_s0<<<dim3(B, 2), 256>>>(in_A, in_edge);
    k_e5<<<dim3(B, 16), 256>>>(in_edge, outE);
    k_residual<<<B, 128>>>(in_prop);

    for (int t = 0; t < 5; t++)
        gru_step<<<BN/16, 256>>>(t & 1, br, bz, bh, bl);

    k_att<<<BN/16, 256>>>(bo, ba1, Wa2, ba2, outO);
    k_final<<<B, 128>>>(outO, res);
}